// round 6
// baseline (speedup 1.0000x reference)
#include <cuda_runtime.h>

#define Bv 8192
#define Nv 256
#define Dv 6
#define Rv 3
#define Hv 32

// packed weights, constant-ready layout:
//   [role*256 + h*8 + {0..5:W1 d, 6:b1, 7:W2}], b2[r] at [768+r]
#define CSTRIDE 256
#define CPACK_WORDS (Rv * CSTRIDE + 4)
__device__   __align__(16) float g_pack[CPACK_WORDS];
__constant__ __align__(16) float c_pack[CPACK_WORDS];
__device__ int g_mask_is_u8;   // 0 = int32 mask, 1 = uint8 mask

__global__ void prep_kernel(const float* __restrict__ W1,
                            const float* __restrict__ b1,
                            const float* __restrict__ W2,
                            const float* __restrict__ b2,
                            const unsigned int* __restrict__ mw) {
    __shared__ int any_gt1;
    const int t = threadIdx.x;
    if (t == 0) any_gt1 = 0;
    __syncthreads();
    int found = 0;
    for (int i = t; i < 4096; i += blockDim.x)   // in-bounds under both mask layouts
        if (mw[i] > 1u) found = 1;
    if (found) any_gt1 = 1;
    __syncthreads();
    if (t == 0) g_mask_is_u8 = any_gt1;

    if (t < Rv * Hv) {
        const int r = t / Hv, h = t % Hv;
        float* dst = g_pack + r * CSTRIDE + h * 8;
        #pragma unroll
        for (int d = 0; d < Dv; d++) dst[d] = W1[r * Dv * Hv + d * Hv + h];
        dst[6] = b1[r * Hv + h];
        dst[7] = W2[r * Hv + h];
    }
    if (t < Rv) g_pack[Rv * CSTRIDE + t] = b2[t];
}

__global__ __launch_bounds__(Nv, 4)
void hmf_encoder_kernel(const float* __restrict__ states,
                        const int*   __restrict__ roles,
                        const void*  __restrict__ maskp,
                        const float* __restrict__ trust,
                        float* __restrict__ out)
{
    __shared__ __align__(16) float sx[Nv * Dv];   // original order, row-major
    __shared__ float sxT[Dv * Nv];                // SORTED order, transposed
    __shared__ float s_twS[Nv];                   // SORTED order trust
    __shared__ float s_e[Nv];                     // sorted order
    __shared__ float s_ew[Nv];                    // sorted order
    __shared__ int   s_perm[Nv];                  // sorted pos -> original idx
    __shared__ int   s_wcnt[8][4];
    __shared__ int   s_woff[8][4];
    __shared__ int   s_tot[4];
    __shared__ int   s_base[5];                   // bucket segment starts
    __shared__ float warp_max[8][3];
    __shared__ float sm[Rv];

    const int b    = blockIdx.x;
    const int tid  = threadIdx.x;
    const int lane = tid & 31;
    const int wid  = tid >> 5;
    const size_t base = (size_t)b * Nv;

    // ================= Phase A: stage + counting sort by bucket =================
    {
        const float4* xb4 = (const float4*)(states + base * Dv);
        float4* sx4 = (float4*)sx;
        #pragma unroll
        for (int i = tid; i < (Nv * Dv) / 4; i += Nv) sx4[i] = xb4[i];
    }

    const int role = roles[base + tid];
    int mk;
    if (g_mask_is_u8) mk = ((const unsigned char*)maskp)[base + tid];
    else              mk = ((const int*)maskp)[base + tid];
    const bool act = (mk != 0);
    const float twv = trust[base + tid];

    const int bucket = act ? role : 3;
    const unsigned m0 = __ballot_sync(0xffffffffu, bucket == 0);
    const unsigned m1 = __ballot_sync(0xffffffffu, bucket == 1);
    const unsigned m2 = __ballot_sync(0xffffffffu, bucket == 2);
    const unsigned m3 = __ballot_sync(0xffffffffu, bucket == 3);
    if (lane == 0) {
        s_wcnt[wid][0] = __popc(m0);
        s_wcnt[wid][1] = __popc(m1);
        s_wcnt[wid][2] = __popc(m2);
        s_wcnt[wid][3] = __popc(m3);
    }
    __syncthreads();

    if (wid == 0) {
        if (lane < 4) {
            int off = 0;
            #pragma unroll
            for (int w = 0; w < 8; w++) { s_woff[w][lane] = off; off += s_wcnt[w][lane]; }
            s_tot[lane] = off;
        }
        __syncwarp();
        if (lane == 0) {
            s_base[0] = 0;
            #pragma unroll
            for (int r = 0; r < 4; r++) s_base[r + 1] = s_base[r] + s_tot[r];
        }
    }
    __syncthreads();

    {
        const unsigned mymask = (bucket == 0) ? m0 : (bucket == 1) ? m1 : (bucket == 2) ? m2 : m3;
        const unsigned lt = (1u << lane) - 1u;
        const int pos = s_base[bucket] + s_woff[wid][bucket] + __popc(mymask & lt);
        s_perm[pos] = tid;
        s_twS[pos]  = twv;   // trust scattered directly into sorted order
    }
    __syncthreads();

    // ================= Phase B: MLP in sorted order (weights via constant port) ==
    const int j = s_perm[tid];
    const int bkt = (tid >= s_base[3]) ? 3 : (tid >= s_base[2]) ? 2 : (tid >= s_base[1]) ? 1 : 0;

    float xj[Dv];
    {
        const float2* xp = (const float2*)sx + j * 3;   // 8B-aligned
        const float2 q0 = xp[0], q1 = xp[1], q2 = xp[2];
        xj[0] = q0.x; xj[1] = q0.y; xj[2] = q1.x; xj[3] = q1.y; xj[4] = q2.x; xj[5] = q2.y;
    }
    #pragma unroll
    for (int d = 0; d < Dv; d++) sxT[d * Nv + tid] = xj[d];   // conflict-free store

    float score = 0.0f;
    if (bkt < Rv) {                       // bucket-3 warps skip the MLP entirely
        const float4* wp = (const float4*)c_pack + (bkt << 6);   // bkt*256/4
        float acc0 = 0.0f, acc1 = 0.0f;
        #pragma unroll
        for (int h = 0; h < Hv; h += 2) {
            const float4 a0 = wp[h * 2];       // warp-uniform LDC (const port)
            const float4 c0 = wp[h * 2 + 1];
            const float4 a1 = wp[h * 2 + 2];
            const float4 c1 = wp[h * 2 + 3];
            float hv0 = fmaf(xj[0], a0.x, fmaf(xj[1], a0.y,
                        fmaf(xj[2], a0.z, fmaf(xj[3], a0.w,
                        fmaf(xj[4], c0.x, fmaf(xj[5], c0.y, c0.z))))));
            float hv1 = fmaf(xj[0], a1.x, fmaf(xj[1], a1.y,
                        fmaf(xj[2], a1.z, fmaf(xj[3], a1.w,
                        fmaf(xj[4], c1.x, fmaf(xj[5], c1.y, c1.z))))));
            acc0 = fmaf(fmaxf(hv0, 0.0f), c0.w, acc0);
            acc1 = fmaf(fmaxf(hv1, 0.0f), c1.w, acc1);
        }
        score = acc0 + acc1 + c_pack[Rv * CSTRIDE + bkt];
    }

    // ---- per-role max (zeros included, matching reference semantics) ----
    float vm0 = 0.0f, vm1 = 0.0f, vm2 = 0.0f;
    if (bkt == 0)      vm0 = score;
    else if (bkt == 1) vm1 = score;
    else if (bkt == 2) vm2 = score;
    #pragma unroll
    for (int o = 16; o; o >>= 1) {
        vm0 = fmaxf(vm0, __shfl_xor_sync(0xffffffffu, vm0, o));
        vm1 = fmaxf(vm1, __shfl_xor_sync(0xffffffffu, vm1, o));
        vm2 = fmaxf(vm2, __shfl_xor_sync(0xffffffffu, vm2, o));
    }
    if (lane == 0) {
        warp_max[wid][0] = vm0;
        warp_max[wid][1] = vm1;
        warp_max[wid][2] = vm2;
    }
    __syncthreads();
    if (tid < Rv) {
        float m = warp_max[0][tid];
        #pragma unroll
        for (int w = 1; w < 8; w++) m = fmaxf(m, warp_max[w][tid]);
        sm[tid] = m;
    }
    __syncthreads();

    // ---- exponentials (sorted order, all stride-1) ----
    float e = 0.0f;
    if (bkt < Rv) e = __expf(score - sm[bkt]);
    s_e[tid]  = e;
    s_ew[tid] = e * s_twS[tid];
    __syncthreads();

    // ================= Reduction: 3 warps, each over its contiguous segment ======
    if (wid < Rv) {
        const int r = wid;
        const int segLo = s_base[r], segHi = s_base[r + 1];
        float den = 0.0f, ws = 0.0f;
        float num[Dv] = {0.f, 0.f, 0.f, 0.f, 0.f, 0.f};
        for (int n0 = segLo; n0 < segHi; n0 += 32) {
            const int n = n0 + lane;
            if (n < segHi) {
                const float ev  = s_e[n];
                const float ewv = s_ew[n];
                den += ev;
                ws  += ewv;
                #pragma unroll
                for (int d = 0; d < Dv; d++)
                    num[d] = fmaf(ewv, sxT[d * Nv + n], num[d]);
            }
        }
        #pragma unroll
        for (int o = 16; o; o >>= 1) {
            den += __shfl_xor_sync(0xffffffffu, den, o);
            ws  += __shfl_xor_sync(0xffffffffu, ws,  o);
            #pragma unroll
            for (int d = 0; d < Dv; d++)
                num[d] += __shfl_xor_sync(0xffffffffu, num[d], o);
        }
        if (lane < Dv) {
            const float inv = 1.0f / (den + 1e-8f);
            const float wsv = fmaxf(ws * inv, 1e-8f);
            out[(size_t)b * (Rv * Dv) + r * Dv + lane] = num[lane] * inv / wsv;
        }
    }
}

extern "C" void kernel_launch(void* const* d_in, const int* in_sizes, int n_in,
                              void* d_out, int out_size) {
    const float* states = (const float*)d_in[0];
    const int*   roles  = (const int*)d_in[1];
    const void*  maskp  = d_in[2];
    const float* trust  = (const float*)d_in[3];
    const float* W1     = (const float*)d_in[4];
    const float* b1     = (const float*)d_in[5];
    const float* W2     = (const float*)d_in[6];
    const float* b2     = (const float*)d_in[7];
    float* out = (float*)d_out;

    prep_kernel<<<1, 256>>>(W1, b1, W2, b2, (const unsigned int*)maskp);

    // copy packed weights into __constant__ (D2D, graph-capturable)
    void* srcAddr = nullptr;
    void* dstAddr = nullptr;
    cudaGetSymbolAddress(&srcAddr, g_pack);
    cudaGetSymbolAddress(&dstAddr, c_pack);
    cudaMemcpyAsync(dstAddr, srcAddr, CPACK_WORDS * sizeof(float),
                    cudaMemcpyDeviceToDevice, 0);

    hmf_encoder_kernel<<<Bv, Nv>>>(states, roles, maskp, trust, out);
}

// round 7
// speedup vs baseline: 1.3173x; 1.3173x over previous
#include <cuda_runtime.h>

#define Bv 8192
#define Nv 256
#define Dv 6
#define Rv 3
#define Hv 32

// packed weights: [role*256 + h*8 + {0..5: W1 d, 6: b1, 7: W2}], b2[r] at [768+r]
#define CSTRIDE 256
#define PACK_WORDS (Rv * CSTRIDE + 4)
__device__ __align__(16) float g_pack[PACK_WORDS];
__device__ int g_mask_is_u8;   // 0 = int32 mask, 1 = uint8 mask

__global__ void prep_kernel(const float* __restrict__ W1,
                            const float* __restrict__ b1,
                            const float* __restrict__ W2,
                            const float* __restrict__ b2,
                            const unsigned int* __restrict__ mw) {
    __shared__ int any_gt1;
    const int t = threadIdx.x;
    if (t == 0) any_gt1 = 0;
    __syncthreads();
    int found = 0;
    for (int i = t; i < 4096; i += blockDim.x)   // in-bounds under both mask layouts
        if (mw[i] > 1u) found = 1;
    if (found) any_gt1 = 1;
    __syncthreads();
    if (t == 0) g_mask_is_u8 = any_gt1;

    if (t < Rv * Hv) {
        const int r = t / Hv, h = t % Hv;
        float* dst = g_pack + r * CSTRIDE + h * 8;
        #pragma unroll
        for (int d = 0; d < Dv; d++) dst[d] = W1[r * Dv * Hv + d * Hv + h];
        dst[6] = b1[r * Hv + h];
        dst[7] = W2[r * Hv + h];
    }
    if (t < Rv) g_pack[Rv * CSTRIDE + t] = b2[t];
}

__global__ __launch_bounds__(Nv, 4)
void hmf_encoder_kernel(const float* __restrict__ states,
                        const int*   __restrict__ roles,
                        const void*  __restrict__ maskp,
                        const float* __restrict__ trust,
                        float* __restrict__ out)
{
    __shared__ __align__(16) float sPack[PACK_WORDS];
    __shared__ float sxT[Dv * Nv];    // SORTED order, transposed
    __shared__ float s_twS[Nv];       // SORTED order trust
    __shared__ float s_e[Nv];         // sorted order
    __shared__ float s_ew[Nv];        // sorted order
    __shared__ int   s_wcnt[8][4];
    __shared__ int   s_woff[8][4];
    __shared__ int   s_tot[4];
    __shared__ int   s_base[5];       // bucket segment starts
    __shared__ float warp_max[8][3];
    __shared__ float sm[Rv];

    const int b    = blockIdx.x;
    const int tid  = threadIdx.x;
    const int lane = tid & 31;
    const int wid  = tid >> 5;
    const size_t base = (size_t)b * Nv;

    // ================= Phase A: per-thread loads + counting sort ================
    // stage packed weights (193 float4s, one per thread for tid<193)
    if (tid < PACK_WORDS / 4) ((float4*)sPack)[tid] = ((const float4*)g_pack)[tid];

    // own neighbor's state: 3 coalesced LDG.64 (stride 24B per lane)
    float xj[Dv];
    {
        const float2* xp = (const float2*)(states + base * Dv) + tid * 3;
        const float2 q0 = xp[0], q1 = xp[1], q2 = xp[2];
        xj[0] = q0.x; xj[1] = q0.y; xj[2] = q1.x; xj[3] = q1.y; xj[4] = q2.x; xj[5] = q2.y;
    }
    const int role = roles[base + tid];
    int mk;
    if (g_mask_is_u8) mk = ((const unsigned char*)maskp)[base + tid];
    else              mk = ((const int*)maskp)[base + tid];
    const bool act = (mk != 0);
    const float twv = trust[base + tid];

    const int bucket = act ? role : 3;
    const unsigned m0 = __ballot_sync(0xffffffffu, bucket == 0);
    const unsigned m1 = __ballot_sync(0xffffffffu, bucket == 1);
    const unsigned m2 = __ballot_sync(0xffffffffu, bucket == 2);
    const unsigned m3 = __ballot_sync(0xffffffffu, bucket == 3);
    if (lane == 0) {
        s_wcnt[wid][0] = __popc(m0);
        s_wcnt[wid][1] = __popc(m1);
        s_wcnt[wid][2] = __popc(m2);
        s_wcnt[wid][3] = __popc(m3);
    }
    __syncthreads();

    if (wid == 0) {
        if (lane < 4) {
            int off = 0;
            #pragma unroll
            for (int w = 0; w < 8; w++) { s_woff[w][lane] = off; off += s_wcnt[w][lane]; }
            s_tot[lane] = off;
        }
        __syncwarp();
        if (lane == 0) {
            s_base[0] = 0;
            #pragma unroll
            for (int r = 0; r < 4; r++) s_base[r + 1] = s_base[r] + s_tot[r];
        }
    }
    __syncthreads();

    // scatter own data into sorted slots (x transposed, trust)
    {
        const unsigned mymask = (bucket == 0) ? m0 : (bucket == 1) ? m1 : (bucket == 2) ? m2 : m3;
        const unsigned lt = (1u << lane) - 1u;
        const int pos = s_base[bucket] + s_woff[wid][bucket] + __popc(mymask & lt);
        #pragma unroll
        for (int d = 0; d < Dv; d++) sxT[d * Nv + pos] = xj[d];
        s_twS[pos] = twv;
    }
    __syncthreads();

    // ================= Phase B: MLP in sorted order (role-uniform warps) ========
    const int bkt = (tid >= s_base[3]) ? 3 : (tid >= s_base[2]) ? 2 : (tid >= s_base[1]) ? 1 : 0;

    float xs[Dv];
    #pragma unroll
    for (int d = 0; d < Dv; d++) xs[d] = sxT[d * Nv + tid];   // conflict-free

    float score = 0.0f;
    if (bkt < Rv) {                        // bucket-3 warps skip the MLP entirely
        const float4* wp = (const float4*)sPack + (bkt << 6);
        float acc0 = 0.0f, acc1 = 0.0f;
        #pragma unroll
        for (int h = 0; h < Hv; h += 2) {
            const float4 a0 = wp[h * 2];       // warp-uniform broadcast LDS.128
            const float4 c0 = wp[h * 2 + 1];
            const float4 a1 = wp[h * 2 + 2];
            const float4 c1 = wp[h * 2 + 3];
            float hv0 = fmaf(xs[0], a0.x, fmaf(xs[1], a0.y,
                        fmaf(xs[2], a0.z, fmaf(xs[3], a0.w,
                        fmaf(xs[4], c0.x, fmaf(xs[5], c0.y, c0.z))))));
            float hv1 = fmaf(xs[0], a1.x, fmaf(xs[1], a1.y,
                        fmaf(xs[2], a1.z, fmaf(xs[3], a1.w,
                        fmaf(xs[4], c1.x, fmaf(xs[5], c1.y, c1.z))))));
            acc0 = fmaf(fmaxf(hv0, 0.0f), c0.w, acc0);
            acc1 = fmaf(fmaxf(hv1, 0.0f), c1.w, acc1);
        }
        score = acc0 + acc1 + sPack[Rv * CSTRIDE + bkt];
    }

    // ---- per-role max (zeros included, matching reference semantics) ----
    float vm0 = 0.0f, vm1 = 0.0f, vm2 = 0.0f;
    if (bkt == 0)      vm0 = score;
    else if (bkt == 1) vm1 = score;
    else if (bkt == 2) vm2 = score;
    #pragma unroll
    for (int o = 16; o; o >>= 1) {
        vm0 = fmaxf(vm0, __shfl_xor_sync(0xffffffffu, vm0, o));
        vm1 = fmaxf(vm1, __shfl_xor_sync(0xffffffffu, vm1, o));
        vm2 = fmaxf(vm2, __shfl_xor_sync(0xffffffffu, vm2, o));
    }
    if (lane == 0) {
        warp_max[wid][0] = vm0;
        warp_max[wid][1] = vm1;
        warp_max[wid][2] = vm2;
    }
    __syncthreads();
    if (tid < Rv) {
        float m = warp_max[0][tid];
        #pragma unroll
        for (int w = 1; w < 8; w++) m = fmaxf(m, warp_max[w][tid]);
        sm[tid] = m;
    }
    __syncthreads();

    // ---- exponentials (sorted order, all stride-1) ----
    float e = 0.0f;
    if (bkt < Rv) e = __expf(score - sm[bkt]);
    s_e[tid]  = e;
    s_ew[tid] = e * s_twS[tid];
    __syncthreads();

    // ================= Reduction: 3 warps, each over its contiguous segment =====
    if (wid < Rv) {
        const int r = wid;
        const int segLo = s_base[r], segHi = s_base[r + 1];
        float den = 0.0f, ws = 0.0f;
        float num[Dv] = {0.f, 0.f, 0.f, 0.f, 0.f, 0.f};
        for (int n0 = segLo; n0 < segHi; n0 += 32) {
            const int n = n0 + lane;
            if (n < segHi) {
                const float ev  = s_e[n];
                const float ewv = s_ew[n];
                den += ev;
                ws  += ewv;
                #pragma unroll
                for (int d = 0; d < Dv; d++)
                    num[d] = fmaf(ewv, sxT[d * Nv + n], num[d]);
            }
        }
        #pragma unroll
        for (int o = 16; o; o >>= 1) {
            den += __shfl_xor_sync(0xffffffffu, den, o);
            ws  += __shfl_xor_sync(0xffffffffu, ws,  o);
            #pragma unroll
            for (int d = 0; d < Dv; d++)
                num[d] += __shfl_xor_sync(0xffffffffu, num[d], o);
        }
        if (lane < Dv) {
            const float inv = 1.0f / (den + 1e-8f);
            const float wsv = fmaxf(ws * inv, 1e-8f);
            out[(size_t)b * (Rv * Dv) + r * Dv + lane] = num[lane] * inv / wsv;
        }
    }
}

extern "C" void kernel_launch(void* const* d_in, const int* in_sizes, int n_in,
                              void* d_out, int out_size) {
    const float* states = (const float*)d_in[0];
    const int*   roles  = (const int*)d_in[1];
    const void*  maskp  = d_in[2];
    const float* trust  = (const float*)d_in[3];
    const float* W1     = (const float*)d_in[4];
    const float* b1     = (const float*)d_in[5];
    const float* W2     = (const float*)d_in[6];
    const float* b2     = (const float*)d_in[7];
    float* out = (float*)d_out;

    prep_kernel<<<1, 256>>>(W1, b1, W2, b2, (const unsigned int*)maskp);
    hmf_encoder_kernel<<<Bv, Nv>>>(states, roles, maskp, trust, out);
}

// round 8
// speedup vs baseline: 1.4958x; 1.1356x over previous
#include <cuda_runtime.h>

#define Bv 8192
#define Nv 256
#define Dv 6
#define Rv 3
#define Hv 32
#define TPB 128

// packed weights: [role*256 + h*8 + {0..5: W1 d, 6: b1, 7: W2}], b2[r] at [768+r]
#define CSTRIDE 256
#define PACK_WORDS (Rv * CSTRIDE + 4)
__device__ __align__(16) float g_pack[PACK_WORDS];
__device__ int g_mask_is_u8;   // 0 = int32 mask, 1 = uint8 mask

__global__ void prep_kernel(const float* __restrict__ W1,
                            const float* __restrict__ b1,
                            const float* __restrict__ W2,
                            const float* __restrict__ b2,
                            const unsigned int* __restrict__ mw) {
    __shared__ int any_gt1;
    const int t = threadIdx.x;
    if (t == 0) any_gt1 = 0;
    __syncthreads();
    int found = 0;
    for (int i = t; i < 4096; i += blockDim.x)   // in-bounds under both mask layouts
        if (mw[i] > 1u) found = 1;
    if (found) any_gt1 = 1;
    __syncthreads();
    if (t == 0) g_mask_is_u8 = any_gt1;

    if (t < Rv * Hv) {
        const int r = t / Hv, h = t % Hv;
        float* dst = g_pack + r * CSTRIDE + h * 8;
        #pragma unroll
        for (int d = 0; d < Dv; d++) dst[d] = W1[r * Dv * Hv + d * Hv + h];
        dst[6] = b1[r * Hv + h];
        dst[7] = W2[r * Hv + h];
    }
    if (t < Rv) g_pack[Rv * CSTRIDE + t] = b2[t];
}

// score of one neighbor (x in .x or .y of xs pairs selected by caller)
__device__ __forceinline__ float mlp_one(const float* __restrict__ wr,
                                         const float x0, const float x1, const float x2,
                                         const float x3, const float x4, const float x5) {
    const float4* wp = (const float4*)wr;
    float acc = 0.0f;
    #pragma unroll
    for (int h = 0; h < Hv; h++) {
        const float4 a = wp[h * 2];
        const float4 c = wp[h * 2 + 1];
        float hv = fmaf(x0, a.x, fmaf(x1, a.y, fmaf(x2, a.z,
                   fmaf(x3, a.w, fmaf(x4, c.x, fmaf(x5, c.y, c.z))))));
        acc = fmaf(fmaxf(hv, 0.0f), c.w, acc);
    }
    return acc;
}

__global__ __launch_bounds__(TPB, 6)
void hmf_encoder_kernel(const float* __restrict__ states,
                        const int*   __restrict__ roles,
                        const void*  __restrict__ maskp,
                        const float* __restrict__ trust,
                        float* __restrict__ out)
{
    __shared__ __align__(16) float sPack[PACK_WORDS];
    __shared__ __align__(16) float sxT[Dv * Nv];   // SORTED order, transposed
    __shared__ __align__(16) float s_twS[Nv];      // SORTED order trust
    __shared__ __align__(16) float s_e[Nv];        // sorted order
    __shared__ __align__(16) float s_ew[Nv];       // sorted order
    __shared__ int   s_wcnt[8][4];                 // virtual-warp counts
    __shared__ int   s_woff[8][4];
    __shared__ int   s_tot[4];
    __shared__ int   s_base[5];                    // bucket segment starts
    __shared__ float warp_max[4][3];
    __shared__ float sm[Rv];

    const int b    = blockIdx.x;
    const int tid  = threadIdx.x;
    const int lane = tid & 31;
    const int wid  = tid >> 5;    // 0..3
    const size_t base = (size_t)b * Nv;

    // ================= Phase A: load 2 neighbors/thread + counting sort =========
    for (int i = tid; i < PACK_WORDS / 4; i += TPB)
        ((float4*)sPack)[i] = ((const float4*)g_pack)[i];

    // neighbors j0 = tid, j1 = tid + 128 (coalesced LDG.64 x3 each)
    float xa[Dv], xc[Dv];
    {
        const float2* xp = (const float2*)(states + base * Dv) + tid * 3;
        float2 q0 = xp[0], q1 = xp[1], q2 = xp[2];
        xa[0]=q0.x; xa[1]=q0.y; xa[2]=q1.x; xa[3]=q1.y; xa[4]=q2.x; xa[5]=q2.y;
        const float2* yp = xp + TPB * 3;
        q0 = yp[0]; q1 = yp[1]; q2 = yp[2];
        xc[0]=q0.x; xc[1]=q0.y; xc[2]=q1.x; xc[3]=q1.y; xc[4]=q2.x; xc[5]=q2.y;
    }
    const int role0 = roles[base + tid];
    const int role1 = roles[base + tid + TPB];
    int mk0, mk1;
    if (g_mask_is_u8) {
        mk0 = ((const unsigned char*)maskp)[base + tid];
        mk1 = ((const unsigned char*)maskp)[base + tid + TPB];
    } else {
        mk0 = ((const int*)maskp)[base + tid];
        mk1 = ((const int*)maskp)[base + tid + TPB];
    }
    const float tw0 = trust[base + tid];
    const float tw1 = trust[base + tid + TPB];

    const int bu0 = (mk0 != 0) ? role0 : 3;
    const int bu1 = (mk1 != 0) ? role1 : 3;

    const unsigned a0 = __ballot_sync(0xffffffffu, bu0 == 0);
    const unsigned a1 = __ballot_sync(0xffffffffu, bu0 == 1);
    const unsigned a2 = __ballot_sync(0xffffffffu, bu0 == 2);
    const unsigned a3 = __ballot_sync(0xffffffffu, bu0 == 3);
    const unsigned c0 = __ballot_sync(0xffffffffu, bu1 == 0);
    const unsigned c1 = __ballot_sync(0xffffffffu, bu1 == 1);
    const unsigned c2 = __ballot_sync(0xffffffffu, bu1 == 2);
    const unsigned c3 = __ballot_sync(0xffffffffu, bu1 == 3);
    if (lane == 0) {
        s_wcnt[wid][0] = __popc(a0);  s_wcnt[wid][1] = __popc(a1);
        s_wcnt[wid][2] = __popc(a2);  s_wcnt[wid][3] = __popc(a3);
        s_wcnt[4 + wid][0] = __popc(c0);  s_wcnt[4 + wid][1] = __popc(c1);
        s_wcnt[4 + wid][2] = __popc(c2);  s_wcnt[4 + wid][3] = __popc(c3);
    }
    __syncthreads();

    if (wid == 0) {
        if (lane < 4) {
            int off = 0;
            #pragma unroll
            for (int w = 0; w < 8; w++) { s_woff[w][lane] = off; off += s_wcnt[w][lane]; }
            s_tot[lane] = off;
        }
        __syncwarp();
        if (lane == 0) {
            s_base[0] = 0;
            #pragma unroll
            for (int r = 0; r < 4; r++) s_base[r + 1] = s_base[r] + s_tot[r];
        }
    }
    __syncthreads();

    // scatter both neighbors into sorted slots (x transposed, trust)
    {
        const unsigned lt = (1u << lane) - 1u;
        const unsigned am = (bu0 == 0) ? a0 : (bu0 == 1) ? a1 : (bu0 == 2) ? a2 : a3;
        const unsigned cm = (bu1 == 0) ? c0 : (bu1 == 1) ? c1 : (bu1 == 2) ? c2 : c3;
        const int pos0 = s_base[bu0] + s_woff[wid][bu0]     + __popc(am & lt);
        const int pos1 = s_base[bu1] + s_woff[4 + wid][bu1] + __popc(cm & lt);
        #pragma unroll
        for (int d = 0; d < Dv; d++) {
            sxT[d * Nv + pos0] = xa[d];
            sxT[d * Nv + pos1] = xc[d];
        }
        s_twS[pos0] = tw0;
        s_twS[pos1] = tw1;
    }
    __syncthreads();

    // ================= Phase B: MLP, 2 adjacent sorted positions per thread =====
    const int p0 = tid * 2;         // even
    const int p1 = p0 + 1;
    const int bkt0 = (p0 >= s_base[3]) ? 3 : (p0 >= s_base[2]) ? 2 : (p0 >= s_base[1]) ? 1 : 0;
    const int bkt1 = (p1 >= s_base[3]) ? 3 : (p1 >= s_base[2]) ? 2 : (p1 >= s_base[1]) ? 1 : 0;

    float2 xs[Dv];
    #pragma unroll
    for (int d = 0; d < Dv; d++) xs[d] = *(const float2*)&sxT[d * Nv + p0];  // LDS.64, conflict-free

    float sc0 = 0.0f, sc1 = 0.0f;
    if (bkt0 < Rv) {      // shared-role fast path: one weight stream feeds both neighbors
        const float4* wp = (const float4*)sPack + (bkt0 << 6);
        float acc0 = 0.0f, acc1 = 0.0f;
        #pragma unroll
        for (int h = 0; h < Hv; h++) {
            const float4 a = wp[h * 2];       // warp-uniform broadcast
            const float4 c = wp[h * 2 + 1];
            float hv0 = fmaf(xs[0].x, a.x, fmaf(xs[1].x, a.y, fmaf(xs[2].x, a.z,
                        fmaf(xs[3].x, a.w, fmaf(xs[4].x, c.x, fmaf(xs[5].x, c.y, c.z))))));
            float hv1 = fmaf(xs[0].y, a.x, fmaf(xs[1].y, a.y, fmaf(xs[2].y, a.z,
                        fmaf(xs[3].y, a.w, fmaf(xs[4].y, c.x, fmaf(xs[5].y, c.y, c.z))))));
            acc0 = fmaf(fmaxf(hv0, 0.0f), c.w, acc0);
            acc1 = fmaf(fmaxf(hv1, 0.0f), c.w, acc1);
        }
        const float bb = sPack[Rv * CSTRIDE + bkt0];
        sc0 = acc0 + bb;
        sc1 = acc1 + bb;
    }
    if (bkt1 != bkt0) {   // rare boundary thread (<= 3 per CTA)
        sc1 = 0.0f;
        if (bkt1 < Rv)
            sc1 = mlp_one(sPack + (bkt1 << 6) * 4 / 4 * 4, // == sPack + bkt1*256
                          xs[0].y, xs[1].y, xs[2].y, xs[3].y, xs[4].y, xs[5].y)
                  + sPack[Rv * CSTRIDE + bkt1];
    }

    // ---- per-role max (zeros included, matching reference semantics) ----
    float vm[Rv] = {0.0f, 0.0f, 0.0f};
    if (bkt0 < Rv) vm[bkt0] = fmaxf(vm[bkt0], sc0);
    if (bkt1 < Rv) vm[bkt1] = fmaxf(vm[bkt1], sc1);
    #pragma unroll
    for (int o = 16; o; o >>= 1) {
        #pragma unroll
        for (int r = 0; r < Rv; r++)
            vm[r] = fmaxf(vm[r], __shfl_xor_sync(0xffffffffu, vm[r], o));
    }
    if (lane == 0) {
        #pragma unroll
        for (int r = 0; r < Rv; r++) warp_max[wid][r] = vm[r];
    }
    __syncthreads();
    if (tid < Rv) {
        float m = warp_max[0][tid];
        #pragma unroll
        for (int w = 1; w < 4; w++) m = fmaxf(m, warp_max[w][tid]);
        sm[tid] = m;
    }
    __syncthreads();

    // ---- exponentials (paired stores) ----
    {
        const float e0 = (bkt0 < Rv) ? __expf(sc0 - sm[bkt0]) : 0.0f;
        const float e1 = (bkt1 < Rv) ? __expf(sc1 - sm[bkt1]) : 0.0f;
        const float2 twp = *(const float2*)&s_twS[p0];
        *(float2*)&s_e[p0]  = make_float2(e0, e1);
        *(float2*)&s_ew[p0] = make_float2(e0 * twp.x, e1 * twp.y);
    }
    __syncthreads();

    // ================= Reduction: 3 warps, each over its contiguous segment =====
    if (wid < Rv) {
        const int r = wid;
        const int segLo = s_base[r], segHi = s_base[r + 1];
        float den = 0.0f, ws = 0.0f;
        float num[Dv] = {0.f, 0.f, 0.f, 0.f, 0.f, 0.f};
        for (int n0 = segLo; n0 < segHi; n0 += 32) {
            const int n = n0 + lane;
            if (n < segHi) {
                const float ev  = s_e[n];
                const float ewv = s_ew[n];
                den += ev;
                ws  += ewv;
                #pragma unroll
                for (int d = 0; d < Dv; d++)
                    num[d] = fmaf(ewv, sxT[d * Nv + n], num[d]);
            }
        }
        #pragma unroll
        for (int o = 16; o; o >>= 1) {
            den += __shfl_xor_sync(0xffffffffu, den, o);
            ws  += __shfl_xor_sync(0xffffffffu, ws,  o);
            #pragma unroll
            for (int d = 0; d < Dv; d++)
                num[d] += __shfl_xor_sync(0xffffffffu, num[d], o);
        }
        if (lane < Dv) {
            const float inv = 1.0f / (den + 1e-8f);
            const float wsv = fmaxf(ws * inv, 1e-8f);
            out[(size_t)b * (Rv * Dv) + r * Dv + lane] = num[lane] * inv / wsv;
        }
    }
}

extern "C" void kernel_launch(void* const* d_in, const int* in_sizes, int n_in,
                              void* d_out, int out_size) {
    const float* states = (const float*)d_in[0];
    const int*   roles  = (const int*)d_in[1];
    const void*  maskp  = d_in[2];
    const float* trust  = (const float*)d_in[3];
    const float* W1     = (const float*)d_in[4];
    const float* b1     = (const float*)d_in[5];
    const float* W2     = (const float*)d_in[6];
    const float* b2     = (const float*)d_in[7];
    float* out = (float*)d_out;

    prep_kernel<<<1, 256>>>(W1, b1, W2, b2, (const unsigned int*)maskp);
    hmf_encoder_kernel<<<Bv, TPB>>>(states, roles, maskp, trust, out);
}

// round 9
// speedup vs baseline: 1.6099x; 1.0762x over previous
#include <cuda_runtime.h>

#define Bv 8192
#define Nv 256
#define Dv 6
#define Rv 3
#define Hv 32
#define TPB 128

// packed weights: [role*256 + h*8 + {0..5: W1 d, 6: b1, 7: W2}], b2[r] at [768+r]
#define CSTRIDE 256
#define PACK_WORDS (Rv * CSTRIDE + 4)
__device__ __align__(16) float g_pack[PACK_WORDS];
__device__ int g_mask_is_u8;   // 0 = int32 mask, 1 = uint8 mask

__global__ void prep_kernel(const float* __restrict__ W1,
                            const float* __restrict__ b1,
                            const float* __restrict__ W2,
                            const float* __restrict__ b2,
                            const unsigned int* __restrict__ mw) {
    __shared__ int any_gt1;
    const int t = threadIdx.x;
    if (t == 0) any_gt1 = 0;
    __syncthreads();
    int found = 0;
    for (int i = t; i < 4096; i += blockDim.x)   // in-bounds under both mask layouts
        if (mw[i] > 1u) found = 1;
    if (found) any_gt1 = 1;
    __syncthreads();
    if (t == 0) g_mask_is_u8 = any_gt1;

    if (t < Rv * Hv) {
        const int r = t / Hv, h = t % Hv;
        float* dst = g_pack + r * CSTRIDE + h * 8;
        #pragma unroll
        for (int d = 0; d < Dv; d++) dst[d] = W1[r * Dv * Hv + d * Hv + h];
        dst[6] = b1[r * Hv + h];
        dst[7] = W2[r * Hv + h];
    }
    if (t < Rv) g_pack[Rv * CSTRIDE + t] = b2[t];
}

// score of one neighbor (boundary-thread fallback)
__device__ __forceinline__ float mlp_one(const float* __restrict__ wr,
                                         const float x0, const float x1, const float x2,
                                         const float x3, const float x4, const float x5) {
    const float4* wp = (const float4*)wr;
    float acc = 0.0f;
    #pragma unroll
    for (int h = 0; h < Hv; h++) {
        const float4 a = wp[h * 2];
        const float4 c = wp[h * 2 + 1];
        float hv = fmaf(x0, a.x, fmaf(x1, a.y, fmaf(x2, a.z,
                   fmaf(x3, a.w, fmaf(x4, c.x, fmaf(x5, c.y, c.z))))));
        acc = fmaf(fmaxf(hv, 0.0f), c.w, acc);
    }
    return acc;
}

__global__ __launch_bounds__(TPB, 7)
void hmf_encoder_kernel(const float* __restrict__ states,
                        const int*   __restrict__ roles,
                        const void*  __restrict__ maskp,
                        const float* __restrict__ trust,
                        float* __restrict__ out)
{
    __shared__ __align__(16) float  sPack[PACK_WORDS];
    __shared__ __align__(16) float2 sxT2[3 * Nv];   // [k][pos] = (x[2k], x[2k+1]), SORTED
    __shared__ __align__(16) float  s_twS[Nv];      // SORTED order trust
    __shared__ __align__(16) float2 s_eew[Nv];      // (e, e*tw), sorted order
    __shared__ int   s_wcnt[8][4];                  // virtual-warp counts
    __shared__ int   s_woff[8][4];
    __shared__ int   s_tot[4];
    __shared__ int   s_base[5];                     // bucket segment starts
    __shared__ float warp_max[4][3];
    __shared__ float sm[Rv];

    const int b    = blockIdx.x;
    const int tid  = threadIdx.x;
    const int lane = tid & 31;
    const int wid  = tid >> 5;    // 0..3
    const size_t base = (size_t)b * Nv;

    // ================= Phase A: load 2 neighbors/thread + counting sort =========
    for (int i = tid; i < PACK_WORDS / 4; i += TPB)
        ((float4*)sPack)[i] = ((const float4*)g_pack)[i];

    // neighbors j0 = tid, j1 = tid + 128 (coalesced LDG.64 x3 each)
    float2 qa0, qa1, qa2, qc0, qc1, qc2;
    {
        const float2* xp = (const float2*)(states + base * Dv) + tid * 3;
        qa0 = xp[0]; qa1 = xp[1]; qa2 = xp[2];
        const float2* yp = xp + TPB * 3;
        qc0 = yp[0]; qc1 = yp[1]; qc2 = yp[2];
    }
    const int role0 = roles[base + tid];
    const int role1 = roles[base + tid + TPB];
    int mk0, mk1;
    if (g_mask_is_u8) {
        mk0 = ((const unsigned char*)maskp)[base + tid];
        mk1 = ((const unsigned char*)maskp)[base + tid + TPB];
    } else {
        mk0 = ((const int*)maskp)[base + tid];
        mk1 = ((const int*)maskp)[base + tid + TPB];
    }
    const float tw0 = trust[base + tid];
    const float tw1 = trust[base + tid + TPB];

    const int bu0 = (mk0 != 0) ? role0 : 3;
    const int bu1 = (mk1 != 0) ? role1 : 3;

    const unsigned a0 = __ballot_sync(0xffffffffu, bu0 == 0);
    const unsigned a1 = __ballot_sync(0xffffffffu, bu0 == 1);
    const unsigned a2 = __ballot_sync(0xffffffffu, bu0 == 2);
    const unsigned a3 = __ballot_sync(0xffffffffu, bu0 == 3);
    const unsigned c0 = __ballot_sync(0xffffffffu, bu1 == 0);
    const unsigned c1 = __ballot_sync(0xffffffffu, bu1 == 1);
    const unsigned c2 = __ballot_sync(0xffffffffu, bu1 == 2);
    const unsigned c3 = __ballot_sync(0xffffffffu, bu1 == 3);
    if (lane == 0) {
        s_wcnt[wid][0] = __popc(a0);  s_wcnt[wid][1] = __popc(a1);
        s_wcnt[wid][2] = __popc(a2);  s_wcnt[wid][3] = __popc(a3);
        s_wcnt[4 + wid][0] = __popc(c0);  s_wcnt[4 + wid][1] = __popc(c1);
        s_wcnt[4 + wid][2] = __popc(c2);  s_wcnt[4 + wid][3] = __popc(c3);
    }
    __syncthreads();

    if (wid == 0) {
        if (lane < 4) {
            int off = 0;
            #pragma unroll
            for (int w = 0; w < 8; w++) { s_woff[w][lane] = off; off += s_wcnt[w][lane]; }
            s_tot[lane] = off;
        }
        __syncwarp();
        if (lane == 0) {
            s_base[0] = 0;
            #pragma unroll
            for (int r = 0; r < 4; r++) s_base[r + 1] = s_base[r] + s_tot[r];
        }
    }
    __syncthreads();

    // scatter both neighbors into sorted slots (x pairs + trust)
    {
        const unsigned lt = (1u << lane) - 1u;
        const unsigned am = (bu0 == 0) ? a0 : (bu0 == 1) ? a1 : (bu0 == 2) ? a2 : a3;
        const unsigned cm = (bu1 == 0) ? c0 : (bu1 == 1) ? c1 : (bu1 == 2) ? c2 : c3;
        const int pos0 = s_base[bu0] + s_woff[wid][bu0]     + __popc(am & lt);
        const int pos1 = s_base[bu1] + s_woff[4 + wid][bu1] + __popc(cm & lt);
        sxT2[0 * Nv + pos0] = qa0;   // 3 STS.64 per neighbor
        sxT2[1 * Nv + pos0] = qa1;
        sxT2[2 * Nv + pos0] = qa2;
        sxT2[0 * Nv + pos1] = qc0;
        sxT2[1 * Nv + pos1] = qc1;
        sxT2[2 * Nv + pos1] = qc2;
        s_twS[pos0] = tw0;
        s_twS[pos1] = tw1;
    }
    __syncthreads();

    // ================= Phase B: MLP, 2 adjacent sorted positions per thread =====
    const int p0 = tid * 2;         // even
    const int p1 = p0 + 1;
    const int bkt0 = (p0 >= s_base[3]) ? 3 : (p0 >= s_base[2]) ? 2 : (p0 >= s_base[1]) ? 1 : 0;
    const int bkt1 = (p1 >= s_base[3]) ? 3 : (p1 >= s_base[2]) ? 2 : (p1 >= s_base[1]) ? 1 : 0;

    // 3 LDS.128: X[k] = {n0.d2k, n0.d2k+1, n1.d2k, n1.d2k+1}
    float4 X0, X1, X2;
    X0 = *(const float4*)&sxT2[0 * Nv + p0];
    X1 = *(const float4*)&sxT2[1 * Nv + p0];
    X2 = *(const float4*)&sxT2[2 * Nv + p0];

    float sc0 = 0.0f, sc1 = 0.0f;
    if (bkt0 < Rv) {      // shared-role fast path: one weight stream feeds both neighbors
        const float4* wp = (const float4*)sPack + (bkt0 << 6);
        float acc0 = 0.0f, acc1 = 0.0f;
        #pragma unroll
        for (int h = 0; h < Hv; h++) {
            const float4 a = wp[h * 2];       // warp-uniform broadcast
            const float4 c = wp[h * 2 + 1];
            float hv0 = fmaf(X0.x, a.x, fmaf(X0.y, a.y, fmaf(X1.x, a.z,
                        fmaf(X1.y, a.w, fmaf(X2.x, c.x, fmaf(X2.y, c.y, c.z))))));
            float hv1 = fmaf(X0.z, a.x, fmaf(X0.w, a.y, fmaf(X1.z, a.z,
                        fmaf(X1.w, a.w, fmaf(X2.z, c.x, fmaf(X2.w, c.y, c.z))))));
            acc0 = fmaf(fmaxf(hv0, 0.0f), c.w, acc0);
            acc1 = fmaf(fmaxf(hv1, 0.0f), c.w, acc1);
        }
        const float bb = sPack[Rv * CSTRIDE + bkt0];
        sc0 = acc0 + bb;
        sc1 = acc1 + bb;
    }
    if (bkt1 != bkt0) {   // rare boundary thread (<= 3 per CTA)
        sc1 = 0.0f;
        if (bkt1 < Rv)
            sc1 = mlp_one(sPack + bkt1 * CSTRIDE,
                          X0.z, X0.w, X1.z, X1.w, X2.z, X2.w)
                  + sPack[Rv * CSTRIDE + bkt1];
    }

    // ---- per-role max (zeros included, matching reference semantics) ----
    float vm[Rv] = {0.0f, 0.0f, 0.0f};
    if (bkt0 < Rv) vm[bkt0] = fmaxf(vm[bkt0], sc0);
    if (bkt1 < Rv) vm[bkt1] = fmaxf(vm[bkt1], sc1);
    #pragma unroll
    for (int o = 16; o; o >>= 1) {
        #pragma unroll
        for (int r = 0; r < Rv; r++)
            vm[r] = fmaxf(vm[r], __shfl_xor_sync(0xffffffffu, vm[r], o));
    }
    if (lane == 0) {
        #pragma unroll
        for (int r = 0; r < Rv; r++) warp_max[wid][r] = vm[r];
    }
    __syncthreads();
    if (tid < Rv) {
        float m = warp_max[0][tid];
        #pragma unroll
        for (int w = 1; w < 4; w++) m = fmaxf(m, warp_max[w][tid]);
        sm[tid] = m;
    }
    __syncthreads();

    // ---- exponentials: store (e, e*tw) packed ----
    {
        const float e0 = (bkt0 < Rv) ? __expf(sc0 - sm[bkt0]) : 0.0f;
        const float e1 = (bkt1 < Rv) ? __expf(sc1 - sm[bkt1]) : 0.0f;
        const float2 twp = *(const float2*)&s_twS[p0];
        s_eew[p0] = make_float2(e0, e0 * twp.x);
        s_eew[p1] = make_float2(e1, e1 * twp.y);
    }
    __syncthreads();

    // ================= Reduction: 3 warps, each over its contiguous segment =====
    if (wid < Rv) {
        const int r = wid;
        const int segLo = s_base[r], segHi = s_base[r + 1];
        float den = 0.0f, ws = 0.0f;
        float num[Dv] = {0.f, 0.f, 0.f, 0.f, 0.f, 0.f};
        for (int n0 = segLo; n0 < segHi; n0 += 32) {
            const int n = n0 + lane;
            if (n < segHi) {
                const float2 ee = s_eew[n];          // LDS.64
                const float2 v0 = sxT2[0 * Nv + n];  // 3x LDS.64, stride-1
                const float2 v1 = sxT2[1 * Nv + n];
                const float2 v2 = sxT2[2 * Nv + n];
                den += ee.x;
                ws  += ee.y;
                num[0] = fmaf(ee.y, v0.x, num[0]);
                num[1] = fmaf(ee.y, v0.y, num[1]);
                num[2] = fmaf(ee.y, v1.x, num[2]);
                num[3] = fmaf(ee.y, v1.y, num[3]);
                num[4] = fmaf(ee.y, v2.x, num[4]);
                num[5] = fmaf(ee.y, v2.y, num[5]);
            }
        }
        #pragma unroll
        for (int o = 16; o; o >>= 1) {
            den += __shfl_xor_sync(0xffffffffu, den, o);
            ws  += __shfl_xor_sync(0xffffffffu, ws,  o);
            #pragma unroll
            for (int d = 0; d < Dv; d++)
                num[d] += __shfl_xor_sync(0xffffffffu, num[d], o);
        }
        if (lane < Dv) {
            const float inv = 1.0f / (den + 1e-8f);
            const float wsv = fmaxf(ws * inv, 1e-8f);
            out[(size_t)b * (Rv * Dv) + r * Dv + lane] = num[lane] * inv / wsv;
        }
    }
}

extern "C" void kernel_launch(void* const* d_in, const int* in_sizes, int n_in,
                              void* d_out, int out_size) {
    const float* states = (const float*)d_in[0];
    const int*   roles  = (const int*)d_in[1];
    const void*  maskp  = d_in[2];
    const float* trust  = (const float*)d_in[3];
    const float* W1     = (const float*)d_in[4];
    const float* b1     = (const float*)d_in[5];
    const float* W2     = (const float*)d_in[6];
    const float* b2     = (const float*)d_in[7];
    float* out = (float*)d_out;

    prep_kernel<<<1, 256>>>(W1, b1, W2, b2, (const unsigned int*)maskp);
    hmf_encoder_kernel<<<Bv, TPB>>>(states, roles, maskp, trust, out);
}